// round 9
// baseline (speedup 1.0000x reference)
#include <cuda_runtime.h>
#include <cstdint>

// Problem constants (fixed by the dataset)
#define BATCH      16
#define NPTS       131072
#define KCENT      1024
#define NBLK       8                     // CTAs per cluster == blocks per batch
#define CHUNK      (NPTS / NBLK)         // 16384 points per block
#define THREADS    512
#define PT_PER_T   (CHUNK / THREADS)     // 32 dist values in registers per thread
#define GROUPS     (PT_PER_T / 4)        // 8 float4 groups per thread
#define NWARP      (THREADS / 32)        // 16

__device__ __forceinline__ uint32_t smem_u32(const void* p) {
    uint32_t a;
    asm("{ .reg .u64 t; cvta.to.shared.u64 t, %1; cvt.u32.u64 %0, t; }"
        : "=r"(a) : "l"(p));
    return a;
}

__device__ __forceinline__ uint32_t mapa_u32(uint32_t addr, uint32_t rank) {
    uint32_t r;
    asm("mapa.shared::cluster.u32 %0, %1, %2;" : "=r"(r) : "r"(addr), "r"(rank));
    return r;
}

__device__ __forceinline__ void cluster_sync_all() {
    asm volatile("barrier.cluster.arrive.aligned;" ::: "memory");
    asm volatile("barrier.cluster.wait.aligned;"   ::: "memory");
}

__global__ void __launch_bounds__(THREADS, 1) __cluster_dims__(NBLK, 1, 1)
fps_kernel(const float* __restrict__ pt, float* __restrict__ out) {
    const int blk = blockIdx.x;          // 0..127
    const int b   = blk / NBLK;          // batch (== cluster id)
    const int sub = blk % NBLK;          // rank within cluster
    const int tid = threadIdx.x;
    const int wid = tid >> 5;
    const int lid = tid & 31;

    extern __shared__ float smem[];      // 3*CHUNK floats = 196608 B
    float* sx = smem;
    float* sy = smem + CHUNK;
    float* sz = smem + 2 * CHUNK;

    __shared__ unsigned long long s_red[NWARP];
    __shared__ unsigned long long s_slots[2][NBLK];   // parity double-buffered
    __shared__ float s_p[3];
    __shared__ int   s_cur;

    const float* px_g = pt + (size_t)b * 3 * NPTS;
    const float* py_g = px_g + NPTS;
    const float* pz_g = px_g + 2 * NPTS;
    const int base = sub * CHUNK;

    // ---- one-time load of this block's coordinate chunk into SMEM (vectorized).
    // SMEM is immune to the per-iteration L1D flush caused by cluster.sync.
    {
        const float4* gx = reinterpret_cast<const float4*>(px_g + base);
        const float4* gy = reinterpret_cast<const float4*>(py_g + base);
        const float4* gz = reinterpret_cast<const float4*>(pz_g + base);
        float4* lx = reinterpret_cast<float4*>(sx);
        float4* ly = reinterpret_cast<float4*>(sy);
        float4* lz = reinterpret_cast<float4*>(sz);
        for (int i = tid; i < CHUNK / 4; i += THREADS) {
            lx[i] = gx[i];
            ly[i] = gy[i];
            lz[i] = gz[i];
        }
    }

    // ---- register-resident min-distance array
    float dist[PT_PER_T];
#pragma unroll
    for (int i = 0; i < PT_PER_T; i++) dist[i] = __int_as_float(0x7f800000);  // +inf

    if (tid == 0) {
        s_cur  = 0;
        s_p[0] = px_g[0];
        s_p[1] = py_g[0];
        s_p[2] = pz_g[0];
    }
    __syncthreads();

    const uint32_t slots_base = smem_u32(&s_slots[0][0]);

    for (int k = 0; k < KCENT; k++) {
        const int   cur = s_cur;
        const float cx = s_p[0], cy = s_p[1], cz = s_p[2];
        const int   p  = k & 1;

        // Output dtype is float32; indices < 2^24 are exact.
        if (sub == 0 && tid == 0) out[b * KCENT + k] = (float)cur;

        // ---- update dists & local argmax (indices ascend -> strict '>' keeps first max)
        float best_d = -1.0f;
        int   best_i = 0;
#pragma unroll
        for (int g = 0; g < GROUPS; g++) {
            const int vi = g * THREADS + tid;
            const float4 x4 = reinterpret_cast<const float4*>(sx)[vi];
            const float4 y4 = reinterpret_cast<const float4*>(sy)[vi];
            const float4 z4 = reinterpret_cast<const float4*>(sz)[vi];
            const int p0 = base + vi * 4;
            const float xs[4] = {x4.x, x4.y, x4.z, x4.w};
            const float ys[4] = {y4.x, y4.y, y4.z, y4.w};
            const float zs[4] = {z4.x, z4.y, z4.z, z4.w};
#pragma unroll
            for (int j = 0; j < 4; j++) {
                // no-FMA-contraction arithmetic, matches reference exactly (rel_err 0.0)
                const float dx = __fadd_rn(xs[j], -cx);
                const float dy = __fadd_rn(ys[j], -cy);
                const float dz = __fadd_rn(zs[j], -cz);
                const float d  = __fadd_rn(__fadd_rn(__fmul_rn(dx, dx),
                                                     __fmul_rn(dy, dy)),
                                           __fmul_rn(dz, dz));
                const float nd = fminf(dist[g * 4 + j], d);
                dist[g * 4 + j] = nd;
                if (nd > best_d) { best_d = nd; best_i = p0 + j; }
            }
        }

        // ---- pack (dist, ~idx): max over packed == max dist, ties -> lowest idx.
        unsigned long long key =
            ((unsigned long long)__float_as_uint(best_d) << 32) |
            (unsigned)(~(unsigned)best_i);

        // warp reduce
#pragma unroll
        for (int off = 16; off > 0; off >>= 1) {
            unsigned long long o = __shfl_down_sync(0xffffffffu, key, off);
            if (o > key) key = o;
        }
        if (lid == 0) s_red[wid] = key;
        __syncthreads();

        // ---- warp 0: final block reduce, then broadcast this block's partial
        // into ALL 8 cluster CTAs' slots via DSMEM (lanes 0..7 in parallel).
        if (wid == 0) {
            unsigned long long v = (lid < NWARP) ? s_red[lid] : 0ull;
#pragma unroll
            for (int off = 8; off > 0; off >>= 1) {
                unsigned long long o = __shfl_down_sync(0xffffffffu, v, off);
                if (o > v) v = o;
            }
            const unsigned long long bb = __shfl_sync(0xffffffffu, v, 0);
            if (lid < NBLK) {
                // local address of s_slots[p][sub], mapped into rank 'lid'
                const uint32_t laddr = slots_base + (uint32_t)(p * NBLK + sub) * 8u;
                const uint32_t raddr = mapa_u32(laddr, (uint32_t)lid);
                asm volatile("st.shared::cluster.u64 [%0], %1;"
                             :: "r"(raddr), "l"(bb) : "memory");
            }
        }

        // cluster barrier: arrive is a release (orders the DSMEM stores),
        // wait is an acquire. HW co-schedules the cluster -> cannot deadlock.
        cluster_sync_all();

        // ---- every CTA reduces its 8 local slots (warp 0, lanes 0..7)
        if (wid == 0) {
            unsigned long long v = (lid < NBLK) ? s_slots[p][lid] : 0ull;
#pragma unroll
            for (int off = 4; off > 0; off >>= 1) {
                unsigned long long o = __shfl_down_sync(0xffffffffu, v, off);
                if (o > v) v = o;
            }
            if (lid == 0) {
                const int nxt = (int)(~(unsigned)(v & 0xffffffffu));
                s_cur  = nxt;
                s_p[0] = px_g[nxt];
                s_p[1] = py_g[nxt];
                s_p[2] = pz_g[nxt];
            }
        }
        __syncthreads();
    }
}

extern "C" void kernel_launch(void* const* d_in, const int* in_sizes, int n_in,
                              void* d_out, int out_size) {
    // Select the coordinate buffer by SIZE, not position: pt has 6291456 elements.
    const float* ptc = nullptr;
    for (int i = 0; i < n_in; i++) {
        if (in_sizes[i] == BATCH * 3 * NPTS) { ptc = (const float*)d_in[i]; break; }
    }
    if (!ptc) {  // fallback: largest input
        int bi = 0;
        for (int i = 1; i < n_in; i++) if (in_sizes[i] > in_sizes[bi]) bi = i;
        ptc = (const float*)d_in[bi];
    }
    float* out = (float*)d_out;
    (void)out_size;

    const int smem_bytes = 3 * CHUNK * sizeof(float);  // 196608 B
    cudaFuncSetAttribute(fps_kernel,
                         cudaFuncAttributeMaxDynamicSharedMemorySize,
                         smem_bytes);

    fps_kernel<<<BATCH * NBLK, THREADS, smem_bytes>>>(ptc, out);
}